// round 11
// baseline (speedup 1.0000x reference)
#include <cuda_runtime.h>
#include <cuda_fp16.h>
#include <cstdint>

// ---------------------------------------------------------------------------
// Problem constants
// ---------------------------------------------------------------------------
#define BATCH    8192
#define HIDDEN   2048
#define NQ       16
#define HALF_DIM 1024

// GEMM tiling: CTA 128(M)x64(N), 4 warps (2Mx2N of 64x32), 3 CTAs/SM.
// BOTH operands fragment-major in gmem -> LDG straight to registers.
// Triple-buffered register pipeline (prefetch distance 2 k16-steps) to cover
// L2 latency (~260cyc) with >=256cyc of own-warp tensor work. No mainloop syncs.
#define BM      128
#define BN      64
#define THREADS 128
#define M_TILES (BATCH / BM)            // 64
#define N_TILES (NQ * HALF_DIM / BN)    // 256
#define NTILES  (M_TILES * N_TILES)     // 16384
#define KSTEPS  (HIDDEN / 16)           // 128 k16 steps

// Fragment record strides (bytes)
//   A record (m16,k16): 32 lanes x 16B = 512B; addr = (m16*128 + k16)*512 + lane*16
//   B record (k16,n8):  32 lanes x  8B = 256B; addr = (k16*2048 + n8)*256 + lane*8
#define A_K16_STRIDE 512u
#define A_M16_STRIDE 65536u             // 128 * 512
#define B_N8_STRIDE  256u
#define B_K16_STRIDE 524288u            // 2048 * 256

// fp16 fragment scratch
__device__ __align__(1024) __half g_Xf[(size_t)BATCH * HIDDEN];              // 32 MB
__device__ __align__(1024) __half g_Wf[(size_t)NQ * HALF_DIM * HIDDEN];     // 64 MB

// ---------------------------------------------------------------------------
// Helpers
// ---------------------------------------------------------------------------
__device__ __forceinline__ void mma16816(float* c, const uint32_t* a, uint2 b) {
    asm volatile(
        "mma.sync.aligned.m16n8k16.row.col.f32.f16.f16.f32 "
        "{%0,%1,%2,%3}, {%4,%5,%6,%7}, {%8,%9}, {%0,%1,%2,%3};"
        : "+f"(c[0]), "+f"(c[1]), "+f"(c[2]), "+f"(c[3])
        : "r"(a[0]), "r"(a[1]), "r"(a[2]), "r"(a[3]), "r"(b.x), "r"(b.y));
}

// ---------------------------------------------------------------------------
// Prepass kernels
// ---------------------------------------------------------------------------
// X[b][h] fp32 -> A fragment records for mma.m16n8k16 row-major A:
// record (m16,k16), lane l: r=l>>2, c=(l&3)*2 (relative);
//   a0={A[r][c],A[r][c+1]}, a1={A[r+8][c],...}, a2={A[r][c+8],...}, a3={A[r+8][c+8],...}
__global__ void prep_xf_kernel(const float* __restrict__ x) {
    int rec  = blockIdx.x * 8 + (threadIdx.x >> 5);  // 0..65535
    int lane = threadIdx.x & 31;
    int m16 = rec >> 7;
    int k16 = rec & 127;
    int r = m16 * 16 + (lane >> 2);
    int c = k16 * 16 + ((lane & 3) << 1);
    const float* p  = x + (size_t)r * HIDDEN + c;
    const float* p8 = p + 8 * HIDDEN;
    union { __half2 h; uint32_t u; } r0, r1, r2, r3;
    r0.h = __floats2half2_rn(p[0],  p[1]);
    r1.h = __floats2half2_rn(p8[0], p8[1]);
    r2.h = __floats2half2_rn(p[8],  p[9]);
    r3.h = __floats2half2_rn(p8[8], p8[9]);
    reinterpret_cast<uint4*>(g_Xf)[(size_t)rec * 32 + lane] =
        make_uint4(r0.u, r1.u, r2.u, r3.u);
}

// W1[q][k][n] (n contiguous) -> B fragment records (bit-exact verified R9/R10):
// record (k16,n8), lane l: n=l>>2, k pairs at 2(l&3) and 2(l&3)+8.
__global__ void prep_wf_kernel(const float* __restrict__ W1) {
    int n8   = blockIdx.x;                               // 0..2047
    int k16  = blockIdx.y * 32 + (threadIdx.x >> 5);     // 0..127
    int lane = threadIdx.x & 31;
    int q = n8 >> 7;
    int n = ((n8 & 127) << 3) + (lane >> 2);
    const float* src = W1 + (size_t)q * HIDDEN * HALF_DIM + n;
    int kb = (k16 << 4) + ((lane & 3) << 1);
    float v0 = src[(size_t)(kb + 0) * HALF_DIM];
    float v1 = src[(size_t)(kb + 1) * HALF_DIM];
    float v2 = src[(size_t)(kb + 8) * HALF_DIM];
    float v3 = src[(size_t)(kb + 9) * HALF_DIM];
    union { __half2 h; uint32_t u; } r0, r1;
    r0.h = __floats2half2_rn(v0, v1);
    r1.h = __floats2half2_rn(v2, v3);
    reinterpret_cast<uint2*>(g_Wf)[((size_t)k16 * 2048 + n8) * 32 + lane] =
        make_uint2(r0.u, r1.u);
}

__global__ void init_out_kernel(float* __restrict__ out, const float* __restrict__ b2) {
    int i = blockIdx.x * blockDim.x + threadIdx.x;
    if (i < BATCH * NQ) out[i] = b2[i & (NQ - 1)];
}

// ---------------------------------------------------------------------------
// Main GEMM + fused GELU/GEMV epilogue — all-register, barrier-free mainloop
// ---------------------------------------------------------------------------
__device__ __forceinline__ void loadA(uint4* a, const char* Ap) {
#pragma unroll
    for (int mi = 0; mi < 4; mi++)
        a[mi] = *reinterpret_cast<const uint4*>(Ap + mi * A_M16_STRIDE);
}
__device__ __forceinline__ void loadB(uint2* b, const char* Bp) {
#pragma unroll
    for (int nj = 0; nj < 4; nj++)
        b[nj] = *reinterpret_cast<const uint2*>(Bp + nj * B_N8_STRIDE);
}
__device__ __forceinline__ void mmastep(float acc[4][4][4], uint4* a, uint2* b) {
#pragma unroll
    for (int mi = 0; mi < 4; mi++)
#pragma unroll
        for (int nj = 0; nj < 4; nj++)
            mma16816(acc[mi][nj], reinterpret_cast<uint32_t*>(&a[mi]), b[nj]);
}

__global__ void __launch_bounds__(THREADS, 3)
gemm_kernel(const float* __restrict__ b1, const float* __restrict__ W2,
            float* __restrict__ out) {
    __shared__ float par[128];          // b1[0:64] | w2[64:128]
    const int tid = threadIdx.x;
    const int wid = tid >> 5;
    const int lid = tid & 31;
    const int wm  = wid >> 1;           // M slab (64 rows), 0..1
    const int wn  = wid & 1;            // N slab (32 cols), 0..1

    // Supertile swizzle: 8(M) x 16(N) CTAs per 128-CTA group
    int cta    = blockIdx.x;
    int super  = cta >> 7;
    int within = cta & 127;
    int m_tile = (super & 7) * 8 + (within & 7);     // 0..63
    int n_tile = (super >> 3) * 16 + (within >> 3);  // 0..255
    int m0     = m_tile * BM;
    int q      = n_tile >> 4;
    int nn     = (n_tile & 15) * BN;

    // Fragment base pointers (advance by one k16 stride per step)
    const char* Ap = (const char*)g_Xf
                   + (size_t)(m_tile * 8 + wm * 4) * A_M16_STRIDE + lid * 16;
    const char* Bp = (const char*)g_Wf
                   + ((size_t)(n_tile * 8 + wn * 4) * 32 + lid) * 8;

    // Epilogue params (single barrier of the whole kernel)
    {
        int col = tid & 63;
        const float* src = (tid < 64) ? b1 : W2;
        par[tid] = src[q * HALF_DIM + nn + col];
    }
    __syncthreads();

    float acc[4][4][4];
#pragma unroll
    for (int mi = 0; mi < 4; mi++)
#pragma unroll
        for (int nj = 0; nj < 4; nj++)
#pragma unroll
            for (int e = 0; e < 4; e++) acc[mi][nj][e] = 0.0f;

    // Triple-buffered pipeline, prefetch distance 2. 128 steps total:
    // prologue loads steps 0,1; loop does 42 x 3 steps (last load = step 127,
    // no OOB); tail computes steps 126,127 from already-loaded buffers.
    uint4 A0[4], A1[4], A2[4];
    uint2 B0[4], B1[4], B2[4];
    loadA(A0, Ap); loadB(B0, Bp); Ap += A_K16_STRIDE; Bp += B_K16_STRIDE;
    loadA(A1, Ap); loadB(B1, Bp); Ap += A_K16_STRIDE; Bp += B_K16_STRIDE;

    for (int it = 0; it < 42; it++) {
        loadA(A2, Ap); loadB(B2, Bp); Ap += A_K16_STRIDE; Bp += B_K16_STRIDE;
        mmastep(acc, A0, B0);
        loadA(A0, Ap); loadB(B0, Bp); Ap += A_K16_STRIDE; Bp += B_K16_STRIDE;
        mmastep(acc, A1, B1);
        loadA(A1, Ap); loadB(B1, Bp); Ap += A_K16_STRIDE; Bp += B_K16_STRIDE;
        mmastep(acc, A2, B2);
    }
    mmastep(acc, A0, B0);   // step 126
    mmastep(acc, A1, B1);   // step 127

    // Epilogue: h = acc + b1; gelu(h) = h * Phi(h); dot with W2; quad-reduce.
    const float* b1s = par;
    const float* w2s = par + 64;
#pragma unroll
    for (int mi = 0; mi < 4; mi++) {
#pragma unroll
        for (int rh = 0; rh < 2; rh++) {
            float v = 0.0f;
#pragma unroll
            for (int nj = 0; nj < 4; nj++) {
                int ncol = wn * 32 + nj * 8 + 2 * (lid & 3);
#pragma unroll
                for (int e = 0; e < 2; e++) {
                    float h = acc[mi][nj][rh * 2 + e] + b1s[ncol + e];
                    v += h * normcdff(h) * w2s[ncol + e];
                }
            }
            v += __shfl_xor_sync(0xFFFFFFFFu, v, 1);
            v += __shfl_xor_sync(0xFFFFFFFFu, v, 2);
            if ((lid & 3) == 0) {
                int mrow = m0 + wm * 64 + mi * 16 + rh * 8 + (lid >> 2);
                atomicAdd(out + (size_t)mrow * NQ + q, v);
            }
        }
    }
}

// ---------------------------------------------------------------------------
// Launch
// ---------------------------------------------------------------------------
extern "C" void kernel_launch(void* const* d_in, const int* in_sizes, int n_in,
                              void* d_out, int out_size) {
    const float* x  = (const float*)d_in[0];
    const float* W1 = (const float*)d_in[1];
    const float* b1 = (const float*)d_in[2];
    const float* W2 = (const float*)d_in[3];
    const float* b2 = (const float*)d_in[4];
    float* out = (float*)d_out;
    (void)in_sizes; (void)n_in; (void)out_size;

    prep_xf_kernel<<<8192, 256>>>(x);
    prep_wf_kernel<<<dim3(2048, 4), 1024>>>(W1);
    init_out_kernel<<<(BATCH * NQ + 255) / 256, 256>>>(out, b2);
    gemm_kernel<<<NTILES, THREADS>>>(b1, W2, out);
}

// round 12
// speedup vs baseline: 1.4532x; 1.4532x over previous
#include <cuda_runtime.h>
#include <cuda_fp16.h>
#include <cstdint>

// ---------------------------------------------------------------------------
// Problem constants
// ---------------------------------------------------------------------------
#define BATCH    8192
#define HIDDEN   2048
#define NQ       16
#define HALF_DIM 1024

// GEMM tiling: CTA 128(M)x128(N), 8 warps (2Mx4N of 64x32), 2 CTAs/SM.
// BOTH operands fragment-major in gmem -> LDG straight to registers.
// Register double-buffer (distance 1), barrier-free mainloop (R10 design),
// 2x bigger CTA tile cuts L2 traffic 12GB -> 8GB (LTS was near saturation).
#define BM      128
#define BN      128
#define THREADS 256
#define M_TILES (BATCH / BM)            // 64
#define N_TILES (NQ * HALF_DIM / BN)    // 128
#define NTILES  (M_TILES * N_TILES)     // 8192
#define KSTEPS  (HIDDEN / 16)           // 128 k16 steps

// Fragment record strides (bytes)
//   A record (m16,k16): 32 lanes x 16B = 512B; addr = (m16*128 + k16)*512 + lane*16
//   B record (k16,n8):  32 lanes x  8B = 256B; addr = (k16*2048 + n8)*256 + lane*8
#define A_K16_STRIDE 512u
#define A_M16_STRIDE 65536u             // 128 * 512
#define B_N8_STRIDE  256u
#define B_K16_STRIDE 524288u            // 2048 * 256

// fp16 fragment scratch
__device__ __align__(1024) __half g_Xf[(size_t)BATCH * HIDDEN];              // 32 MB
__device__ __align__(1024) __half g_Wf[(size_t)NQ * HALF_DIM * HIDDEN];     // 64 MB

// ---------------------------------------------------------------------------
// Helpers
// ---------------------------------------------------------------------------
__device__ __forceinline__ void mma16816(float* c, const uint32_t* a, uint2 b) {
    asm volatile(
        "mma.sync.aligned.m16n8k16.row.col.f32.f16.f16.f32 "
        "{%0,%1,%2,%3}, {%4,%5,%6,%7}, {%8,%9}, {%0,%1,%2,%3};"
        : "+f"(c[0]), "+f"(c[1]), "+f"(c[2]), "+f"(c[3])
        : "r"(a[0]), "r"(a[1]), "r"(a[2]), "r"(a[3]), "r"(b.x), "r"(b.y));
}

// ---------------------------------------------------------------------------
// Prepass kernels (fragment layouts bit-exact verified R9/R10)
// ---------------------------------------------------------------------------
__global__ void prep_xf_kernel(const float* __restrict__ x) {
    int rec  = blockIdx.x * 8 + (threadIdx.x >> 5);  // 0..65535
    int lane = threadIdx.x & 31;
    int m16 = rec >> 7;
    int k16 = rec & 127;
    int r = m16 * 16 + (lane >> 2);
    int c = k16 * 16 + ((lane & 3) << 1);
    const float* p  = x + (size_t)r * HIDDEN + c;
    const float* p8 = p + 8 * HIDDEN;
    union { __half2 h; uint32_t u; } r0, r1, r2, r3;
    r0.h = __floats2half2_rn(p[0],  p[1]);
    r1.h = __floats2half2_rn(p8[0], p8[1]);
    r2.h = __floats2half2_rn(p[8],  p[9]);
    r3.h = __floats2half2_rn(p8[8], p8[9]);
    reinterpret_cast<uint4*>(g_Xf)[(size_t)rec * 32 + lane] =
        make_uint4(r0.u, r1.u, r2.u, r3.u);
}

__global__ void prep_wf_kernel(const float* __restrict__ W1) {
    int n8   = blockIdx.x;                               // 0..2047
    int k16  = blockIdx.y * 32 + (threadIdx.x >> 5);     // 0..127
    int lane = threadIdx.x & 31;
    int q = n8 >> 7;
    int n = ((n8 & 127) << 3) + (lane >> 2);
    const float* src = W1 + (size_t)q * HIDDEN * HALF_DIM + n;
    int kb = (k16 << 4) + ((lane & 3) << 1);
    float v0 = src[(size_t)(kb + 0) * HALF_DIM];
    float v1 = src[(size_t)(kb + 1) * HALF_DIM];
    float v2 = src[(size_t)(kb + 8) * HALF_DIM];
    float v3 = src[(size_t)(kb + 9) * HALF_DIM];
    union { __half2 h; uint32_t u; } r0, r1;
    r0.h = __floats2half2_rn(v0, v1);
    r1.h = __floats2half2_rn(v2, v3);
    reinterpret_cast<uint2*>(g_Wf)[((size_t)k16 * 2048 + n8) * 32 + lane] =
        make_uint2(r0.u, r1.u);
}

__global__ void init_out_kernel(float* __restrict__ out, const float* __restrict__ b2) {
    int i = blockIdx.x * blockDim.x + threadIdx.x;
    if (i < BATCH * NQ) out[i] = b2[i & (NQ - 1)];
}

// ---------------------------------------------------------------------------
// Main GEMM + fused GELU/GEMV epilogue — all-register, barrier-free mainloop
// ---------------------------------------------------------------------------
__device__ __forceinline__ void loadA(uint4* a, const char* Ap) {
#pragma unroll
    for (int mi = 0; mi < 4; mi++)
        a[mi] = *reinterpret_cast<const uint4*>(Ap + mi * A_M16_STRIDE);
}
__device__ __forceinline__ void loadB(uint2* b, const char* Bp) {
#pragma unroll
    for (int nj = 0; nj < 4; nj++)
        b[nj] = *reinterpret_cast<const uint2*>(Bp + nj * B_N8_STRIDE);
}
__device__ __forceinline__ void mmastep(float acc[4][4][4], uint4* a, uint2* b) {
#pragma unroll
    for (int mi = 0; mi < 4; mi++)
#pragma unroll
        for (int nj = 0; nj < 4; nj++)
            mma16816(acc[mi][nj], reinterpret_cast<uint32_t*>(&a[mi]), b[nj]);
}

__global__ void __launch_bounds__(THREADS, 2)
gemm_kernel(const float* __restrict__ b1, const float* __restrict__ W2,
            float* __restrict__ out) {
    __shared__ float par[256];          // b1[0:128] | w2[128:256]
    const int tid = threadIdx.x;
    const int wid = tid >> 5;
    const int lid = tid & 31;
    const int wm  = wid >> 2;           // M slab (64 rows), 0..1
    const int wn  = wid & 3;            // N slab (32 cols), 0..3

    // Supertile swizzle: 8(M) x 16(N) CTAs per 128-CTA group
    int cta    = blockIdx.x;
    int super  = cta >> 7;              // 0..63
    int within = cta & 127;
    int m_tile = (super & 7) * 8 + (within & 7);     // 0..63
    int n_tile = (super >> 3) * 16 + (within >> 3);  // 0..127
    int m0     = m_tile * BM;
    int q      = n_tile >> 3;
    int nn     = (n_tile & 7) * BN;

    // Fragment base pointers (advance by one k16 stride per step)
    const char* Ap = (const char*)g_Xf
                   + (size_t)(m_tile * 8 + wm * 4) * A_M16_STRIDE + lid * 16;
    const char* Bp = (const char*)g_Wf
                   + ((size_t)(n_tile * 16 + wn * 4) * 32 + lid) * 8;

    // Epilogue params (single barrier of the whole kernel)
    {
        int col = tid & 127;
        const float* src = (tid < 128) ? b1 : W2;
        par[tid] = src[q * HALF_DIM + nn + col];
    }
    __syncthreads();

    float acc[4][4][4];
#pragma unroll
    for (int mi = 0; mi < 4; mi++)
#pragma unroll
        for (int nj = 0; nj < 4; nj++)
#pragma unroll
            for (int e = 0; e < 4; e++) acc[mi][nj][e] = 0.0f;

    // Register double-buffer, prefetch distance 1, loop peeled so the last
    // load is step 127 (no OOB, no pad needed).
    uint4 A0[4], A1[4];
    uint2 B0[4], B1[4];
    loadA(A0, Ap); loadB(B0, Bp);
    Ap += A_K16_STRIDE; Bp += B_K16_STRIDE;

    for (int s = 0; s < KSTEPS - 2; s += 2) {
        loadA(A1, Ap); loadB(B1, Bp);
        Ap += A_K16_STRIDE; Bp += B_K16_STRIDE;
        mmastep(acc, A0, B0);
        loadA(A0, Ap); loadB(B0, Bp);
        Ap += A_K16_STRIDE; Bp += B_K16_STRIDE;
        mmastep(acc, A1, B1);
    }
    // steps 126, 127 (loads step 127 only)
    loadA(A1, Ap); loadB(B1, Bp);
    mmastep(acc, A0, B0);
    mmastep(acc, A1, B1);

    // Epilogue: h = acc + b1; gelu(h) = h * Phi(h); dot with W2; quad-reduce.
    const float* b1s = par;
    const float* w2s = par + 128;
#pragma unroll
    for (int mi = 0; mi < 4; mi++) {
#pragma unroll
        for (int rh = 0; rh < 2; rh++) {
            float v = 0.0f;
#pragma unroll
            for (int nj = 0; nj < 4; nj++) {
                int ncol = wn * 32 + nj * 8 + 2 * (lid & 3);
#pragma unroll
                for (int e = 0; e < 2; e++) {
                    float h = acc[mi][nj][rh * 2 + e] + b1s[ncol + e];
                    v += h * normcdff(h) * w2s[ncol + e];
                }
            }
            v += __shfl_xor_sync(0xFFFFFFFFu, v, 1);
            v += __shfl_xor_sync(0xFFFFFFFFu, v, 2);
            if ((lid & 3) == 0) {
                int mrow = m0 + wm * 64 + mi * 16 + rh * 8 + (lid >> 2);
                atomicAdd(out + (size_t)mrow * NQ + q, v);
            }
        }
    }
}

// ---------------------------------------------------------------------------
// Launch
// ---------------------------------------------------------------------------
extern "C" void kernel_launch(void* const* d_in, const int* in_sizes, int n_in,
                              void* d_out, int out_size) {
    const float* x  = (const float*)d_in[0];
    const float* W1 = (const float*)d_in[1];
    const float* b1 = (const float*)d_in[2];
    const float* W2 = (const float*)d_in[3];
    const float* b2 = (const float*)d_in[4];
    float* out = (float*)d_out;
    (void)in_sizes; (void)n_in; (void)out_size;

    prep_xf_kernel<<<8192, 256>>>(x);
    prep_wf_kernel<<<dim3(2048, 4), 1024>>>(W1);
    init_out_kernel<<<(BATCH * NQ + 255) / 256, 256>>>(out, b2);
    gemm_kernel<<<NTILES, THREADS>>>(b1, W2, out);
}

// round 13
// speedup vs baseline: 1.5173x; 1.0441x over previous
#include <cuda_runtime.h>
#include <cuda_fp16.h>
#include <cstdint>

// ---------------------------------------------------------------------------
// Problem constants
// ---------------------------------------------------------------------------
#define BATCH    8192
#define HIDDEN   2048
#define NQ       16
#define HALF_DIM 1024

// GEMM tiling: CTA 128(M)x64(N), 4 warps (2Mx2N of 64x32), 4 CTAs/SM.
// BOTH operands fragment-major in gmem -> LDG straight to registers.
// Register double-buffer, barrier-free mainloop. (R10 config — best measured.)
#define BM      128
#define BN      64
#define THREADS 128
#define M_TILES (BATCH / BM)            // 64
#define N_TILES (NQ * HALF_DIM / BN)    // 256
#define NTILES  (M_TILES * N_TILES)     // 16384
#define KSTEPS  (HIDDEN / 16)           // 128 k16 steps

// Fragment record strides (bytes)
//   A record (m16,k16): 32 lanes x 16B = 512B; addr = (m16*128 + k16)*512 + lane*16
//   B record (k16,n8):  32 lanes x  8B = 256B; addr = (k16*2048 + n8)*256 + lane*8
#define A_K16_STRIDE 512u
#define A_M16_STRIDE 65536u             // 128 * 512
#define B_N8_STRIDE  256u
#define B_K16_STRIDE 524288u            // 2048 * 256

// fp16 fragment scratch (+pad for the pipeline's final dead prefetch)
__device__ __align__(1024) __half g_Xf[(size_t)BATCH * HIDDEN + 512];          // 32 MB + 1KB
__device__ __align__(1024) __half g_Wf[(size_t)NQ * HALF_DIM * HIDDEN + 8192]; // 64 MB + 16KB

// ---------------------------------------------------------------------------
// Helpers
// ---------------------------------------------------------------------------
__device__ __forceinline__ void mma16816(float* c, const uint32_t* a, uint2 b) {
    asm volatile(
        "mma.sync.aligned.m16n8k16.row.col.f32.f16.f16.f32 "
        "{%0,%1,%2,%3}, {%4,%5,%6,%7}, {%8,%9}, {%0,%1,%2,%3};"
        : "+f"(c[0]), "+f"(c[1]), "+f"(c[2]), "+f"(c[3])
        : "r"(a[0]), "r"(a[1]), "r"(a[2]), "r"(a[3]), "r"(b.x), "r"(b.y));
}

// ---------------------------------------------------------------------------
// Prepass kernels
// ---------------------------------------------------------------------------
// X[b][h] fp32 -> A fragment records (layout bit-exact verified R10):
// record (m16,k16), lane l: r=l>>2, c=(l&3)*2 (relative);
//   a0={A[r][c],A[r][c+1]}, a1={A[r+8][c],...}, a2={A[r][c+8],...}, a3={A[r+8][c+8],...}
__global__ void prep_xf_kernel(const float* __restrict__ x) {
    int rec  = blockIdx.x * 8 + (threadIdx.x >> 5);  // 0..65535
    int lane = threadIdx.x & 31;
    int m16 = rec >> 7;
    int k16 = rec & 127;
    int r = m16 * 16 + (lane >> 2);
    int c = k16 * 16 + ((lane & 3) << 1);
    const float* p  = x + (size_t)r * HIDDEN + c;
    const float* p8 = p + 8 * HIDDEN;
    union { __half2 h; uint32_t u; } r0, r1, r2, r3;
    r0.h = __floats2half2_rn(p[0],  p[1]);
    r1.h = __floats2half2_rn(p8[0], p8[1]);
    r2.h = __floats2half2_rn(p[8],  p[9]);
    r3.h = __floats2half2_rn(p8[8], p8[9]);
    reinterpret_cast<uint4*>(g_Xf)[(size_t)rec * 32 + lane] =
        make_uint4(r0.u, r1.u, r2.u, r3.u);
}

// W1[q][k][n] -> B fragment records, coalesced via smem tile.
// Block = (nb, k16, q): loads 16 W1 rows x 256 n (coalesced 1KB/row), emits
// 32 records (k16, n8) with conflict-free smem gathers + 256B coalesced stores.
// Record semantics identical to R9-R12 (bit-exact verified): lane l holds
// n = n8*8 + (l>>2); k pairs at k16*16 + 2(l&3) + {0,1} and + {8,9}.
#define PW_S 260   // smem row stride (floats): bank = (8i + j + 8*n8l) % 32, all distinct
__global__ void prep_wf_kernel(const float* __restrict__ W1) {
    __shared__ float s[16 * PW_S];
    int nb  = blockIdx.x;       // 0..3   (256-wide n block)
    int k16 = blockIdx.y;       // 0..127
    int q   = blockIdx.z;       // 0..15
    int t   = threadIdx.x;      // 256 threads
    const float* src = W1 + ((size_t)q * HIDDEN + k16 * 16) * HALF_DIM + nb * 256;
#pragma unroll
    for (int i = 0; i < 16; i++)
        s[i * PW_S + t] = src[(size_t)i * HALF_DIM + t];
    __syncthreads();
    int lane = t & 31;
    int w    = t >> 5;          // 8 warps x 4 records = 32 records
#pragma unroll
    for (int rr = 0; rr < 4; rr++) {
        int n8l = w * 4 + rr;                   // 0..31
        int nl  = n8l * 8 + (lane >> 2);        // n within 256 block
        int kb  = (lane & 3) << 1;              // 0,2,4,6
        union { __half2 h; uint32_t u; } r0, r1;
        r0.h = __floats2half2_rn(s[(kb + 0) * PW_S + nl], s[(kb + 1) * PW_S + nl]);
        r1.h = __floats2half2_rn(s[(kb + 8) * PW_S + nl], s[(kb + 9) * PW_S + nl]);
        int n8g = q * 128 + nb * 32 + n8l;      // global n8 0..2047
        reinterpret_cast<uint2*>(g_Wf)[((size_t)k16 * 2048 + n8g) * 32 + lane] =
            make_uint2(r0.u, r1.u);
    }
}

__global__ void init_out_kernel(float* __restrict__ out, const float* __restrict__ b2) {
    int i = blockIdx.x * blockDim.x + threadIdx.x;
    if (i < BATCH * NQ) out[i] = b2[i & (NQ - 1)];
}

// ---------------------------------------------------------------------------
// Main GEMM + fused GELU/GEMV epilogue — all-register, barrier-free mainloop
// (byte-identical to R10, the best measured configuration)
// ---------------------------------------------------------------------------
__device__ __forceinline__ void loadA(uint4* a, const char* Ap) {
#pragma unroll
    for (int mi = 0; mi < 4; mi++)
        a[mi] = *reinterpret_cast<const uint4*>(Ap + mi * A_M16_STRIDE);
}
__device__ __forceinline__ void loadB(uint2* b, const char* Bp) {
#pragma unroll
    for (int nj = 0; nj < 4; nj++)
        b[nj] = *reinterpret_cast<const uint2*>(Bp + nj * B_N8_STRIDE);
}

__global__ void __launch_bounds__(THREADS, 4)
gemm_kernel(const float* __restrict__ b1, const float* __restrict__ W2,
            float* __restrict__ out) {
    __shared__ float par[128];          // b1[0:64] | w2[64:128]
    const int tid = threadIdx.x;
    const int wid = tid >> 5;
    const int lid = tid & 31;
    const int wm  = wid >> 1;           // M slab (64 rows), 0..1
    const int wn  = wid & 1;            // N slab (32 cols), 0..1

    // Supertile swizzle: 8(M) x 16(N) CTAs per 128-CTA group
    int cta    = blockIdx.x;
    int super  = cta >> 7;
    int within = cta & 127;
    int m_tile = (super & 7) * 8 + (within & 7);     // 0..63
    int n_tile = (super >> 3) * 16 + (within >> 3);  // 0..255
    int m0     = m_tile * BM;
    int q      = n_tile >> 4;
    int nn     = (n_tile & 15) * BN;

    // Fragment base pointers (advance by one k16 stride per step)
    const char* Ap = (const char*)g_Xf
                   + (size_t)(m_tile * 8 + wm * 4) * A_M16_STRIDE + lid * 16;
    const char* Bp = (const char*)g_Wf
                   + ((size_t)(n_tile * 8 + wn * 4) * 32 + lid) * 8;

    // Epilogue params (single barrier of the whole kernel)
    {
        int col = tid & 63;
        const float* src = (tid < 64) ? b1 : W2;
        par[tid] = src[q * HALF_DIM + nn + col];
    }
    __syncthreads();

    float acc[4][4][4];
#pragma unroll
    for (int mi = 0; mi < 4; mi++)
#pragma unroll
        for (int nj = 0; nj < 4; nj++)
#pragma unroll
            for (int e = 0; e < 4; e++) acc[mi][nj][e] = 0.0f;

    // Software pipeline: register double-buffer, prefetch distance 1 step.
    uint4 a0[4], a1[4];
    uint2 b0[4], b1f[4];
    loadA(a0, Ap); loadB(b0, Bp);
    Ap += A_K16_STRIDE; Bp += B_K16_STRIDE;

    for (int s = 0; s < KSTEPS; s += 2) {
        // prefetch step s+1
        loadA(a1, Ap); loadB(b1f, Bp);
        Ap += A_K16_STRIDE; Bp += B_K16_STRIDE;
        // mma step s
#pragma unroll
        for (int mi = 0; mi < 4; mi++)
#pragma unroll
            for (int nj = 0; nj < 4; nj++)
                mma16816(acc[mi][nj], reinterpret_cast<uint32_t*>(&a0[mi]), b0[nj]);
        // prefetch step s+2 (final iteration reads into pad; unused)
        loadA(a0, Ap); loadB(b0, Bp);
        Ap += A_K16_STRIDE; Bp += B_K16_STRIDE;
        // mma step s+1
#pragma unroll
        for (int mi = 0; mi < 4; mi++)
#pragma unroll
            for (int nj = 0; nj < 4; nj++)
                mma16816(acc[mi][nj], reinterpret_cast<uint32_t*>(&a1[mi]), b1f[nj]);
    }

    // Epilogue: h = acc + b1; gelu(h) = h * Phi(h); dot with W2; quad-reduce.
    const float* b1s = par;
    const float* w2s = par + 64;
#pragma unroll
    for (int mi = 0; mi < 4; mi++) {
#pragma unroll
        for (int rh = 0; rh < 2; rh++) {
            float v = 0.0f;
#pragma unroll
            for (int nj = 0; nj < 4; nj++) {
                int ncol = wn * 32 + nj * 8 + 2 * (lid & 3);
#pragma unroll
                for (int e = 0; e < 2; e++) {
                    float h = acc[mi][nj][rh * 2 + e] + b1s[ncol + e];
                    v += h * normcdff(h) * w2s[ncol + e];
                }
            }
            v += __shfl_xor_sync(0xFFFFFFFFu, v, 1);
            v += __shfl_xor_sync(0xFFFFFFFFu, v, 2);
            if ((lid & 3) == 0) {
                int mrow = m0 + wm * 64 + mi * 16 + rh * 8 + (lid >> 2);
                atomicAdd(out + (size_t)mrow * NQ + q, v);
            }
        }
    }
}

// ---------------------------------------------------------------------------
// Launch
// ---------------------------------------------------------------------------
extern "C" void kernel_launch(void* const* d_in, const int* in_sizes, int n_in,
                              void* d_out, int out_size) {
    const float* x  = (const float*)d_in[0];
    const float* W1 = (const float*)d_in[1];
    const float* b1 = (const float*)d_in[2];
    const float* W2 = (const float*)d_in[3];
    const float* b2 = (const float*)d_in[4];
    float* out = (float*)d_out;
    (void)in_sizes; (void)n_in; (void)out_size;

    prep_xf_kernel<<<8192, 256>>>(x);
    prep_wf_kernel<<<dim3(4, 128, 16), 256>>>(W1);
    init_out_kernel<<<(BATCH * NQ + 255) / 256, 256>>>(out, b2);
    gemm_kernel<<<NTILES, THREADS>>>(b1, W2, out);
}

// round 14
// speedup vs baseline: 1.5504x; 1.0218x over previous
#include <cuda_runtime.h>
#include <cuda_fp16.h>
#include <cstdint>

// ---------------------------------------------------------------------------
// Problem constants
// ---------------------------------------------------------------------------
#define BATCH    8192
#define HIDDEN   2048
#define NQ       16
#define HALF_DIM 1024

// GEMM tiling: CTA 128(M)x64(N), 4 warps (2Mx2N of 64x32), 4 CTAs/SM.
// BOTH operands fragment-major in gmem -> LDG straight to registers.
// Register double-buffer, barrier-free mainloop (R10/R13 measured-best).
// B records packed as (k16,n16) so loadB = 2x LDG.128.
#define BM      128
#define BN      64
#define THREADS 128
#define M_TILES (BATCH / BM)            // 64
#define N_TILES (NQ * HALF_DIM / BN)    // 256
#define NTILES  (M_TILES * N_TILES)     // 16384
#define KSTEPS  (HIDDEN / 16)           // 128 k16 steps

// Fragment record strides (bytes)
//   A record (m16,k16): 32 lanes x 16B = 512B; addr = (m16*128 + k16)*512 + lane*16
//   B record (k16,n16): 32 lanes x 16B = 512B; addr = (k16*1024 + n16)*512 + lane*16
//     lane 16B = {n8even.r0, n8even.r1, n8odd.r0, n8odd.r1}
#define A_K16_STRIDE 512u
#define A_M16_STRIDE 65536u             // 128 * 512
#define B_N16_STRIDE 512u
#define B_K16_STRIDE 524288u            // 1024 * 512

// fp16 fragment scratch (pads retained defensively; mainloop has no OOB reads)
__device__ __align__(1024) __half g_Xf[(size_t)BATCH * HIDDEN + 512];
__device__ __align__(1024) __half g_Wf[(size_t)NQ * HALF_DIM * HIDDEN + 8192];

// ---------------------------------------------------------------------------
// Helpers
// ---------------------------------------------------------------------------
__device__ __forceinline__ void mma16816(float* c, const uint32_t* a, uint2 b) {
    asm volatile(
        "mma.sync.aligned.m16n8k16.row.col.f32.f16.f16.f32 "
        "{%0,%1,%2,%3}, {%4,%5,%6,%7}, {%8,%9}, {%0,%1,%2,%3};"
        : "+f"(c[0]), "+f"(c[1]), "+f"(c[2]), "+f"(c[3])
        : "r"(a[0]), "r"(a[1]), "r"(a[2]), "r"(a[3]), "r"(b.x), "r"(b.y));
}

// ---------------------------------------------------------------------------
// Fused prepass: one launch, block-range dispatch.
//   blocks [0, 8192)      : W1 -> B fragment records (smem-tiled, coalesced)
//   blocks [8192, 12288)  : x  -> A fragment records (smem-tiled, coalesced)
//   blocks [12288, 12800) : out = b2 broadcast
// ---------------------------------------------------------------------------
#define PS 260                            // smem row stride (floats)
#define PREP_SMEM (16 * PS * 4)           // 16640 bytes

__global__ void prep_all_kernel(const float* __restrict__ W1,
                                const float* __restrict__ x,
                                float* __restrict__ out,
                                const float* __restrict__ b2) {
    extern __shared__ float s[];
    int bid = blockIdx.x;
    int t   = threadIdx.x;                // 256 threads

    if (bid < 8192) {
        // ---- W prep: block = (nb, k16, q) ----
        int nb  = bid & 3;
        int k16 = (bid >> 2) & 127;
        int q   = bid >> 9;
        const float* src = W1 + ((size_t)q * HIDDEN + k16 * 16) * HALF_DIM + nb * 256;
#pragma unroll
        for (int i = 0; i < 16; i++)
            s[i * PS + t] = src[(size_t)i * HALF_DIM + t];
        __syncthreads();
        int lane = t & 31;
        int w    = t >> 5;
#pragma unroll
        for (int p = 0; p < 2; p++) {
            int n16l = w * 2 + p;                   // 0..15
            int nl   = n16l * 16 + (lane >> 2);     // n8even col within 256
            int kb   = (lane & 3) << 1;
            union { __half2 h; uint32_t u; } e0, e1, o0, o1;
            e0.h = __floats2half2_rn(s[(kb + 0) * PS + nl],     s[(kb + 1) * PS + nl]);
            e1.h = __floats2half2_rn(s[(kb + 8) * PS + nl],     s[(kb + 9) * PS + nl]);
            o0.h = __floats2half2_rn(s[(kb + 0) * PS + nl + 8], s[(kb + 1) * PS + nl + 8]);
            o1.h = __floats2half2_rn(s[(kb + 8) * PS + nl + 8], s[(kb + 9) * PS + nl + 8]);
            int n16g = q * 64 + nb * 16 + n16l;     // 0..1023
            reinterpret_cast<uint4*>(g_Wf)[((size_t)k16 * 1024 + n16g) * 32 + lane] =
                make_uint4(e0.u, e1.u, o0.u, o1.u);
        }
    } else if (bid < 12288) {
        // ---- X prep: block = (m16, kb of 256 cols) ----
        int idx = bid - 8192;
        int m16 = idx >> 3;
        int kb  = idx & 7;
        const float* src = x + (size_t)(m16 * 16) * HIDDEN + kb * 256;
#pragma unroll
        for (int i = 0; i < 16; i++)
            s[i * PS + t] = src[(size_t)i * HIDDEN + t];
        __syncthreads();
        int lane = t & 31;
        int w    = t >> 5;
#pragma unroll
        for (int p = 0; p < 2; p++) {
            int k16l = w * 2 + p;                   // 0..15
            int r    = lane >> 2;
            int base = k16l * 16 + ((lane & 3) << 1);
            union { __half2 h; uint32_t u; } a0, a1, a2, a3;
            a0.h = __floats2half2_rn(s[r * PS + base],           s[r * PS + base + 1]);
            a1.h = __floats2half2_rn(s[(r + 8) * PS + base],     s[(r + 8) * PS + base + 1]);
            a2.h = __floats2half2_rn(s[r * PS + base + 8],       s[r * PS + base + 9]);
            a3.h = __floats2half2_rn(s[(r + 8) * PS + base + 8], s[(r + 8) * PS + base + 9]);
            int rec = m16 * 128 + kb * 16 + k16l;
            reinterpret_cast<uint4*>(g_Xf)[(size_t)rec * 32 + lane] =
                make_uint4(a0.u, a1.u, a2.u, a3.u);
        }
    } else {
        // ---- out init: 512 blocks x 256 = 131072 = BATCH*NQ ----
        int i = (bid - 12288) * 256 + t;
        out[i] = b2[i & (NQ - 1)];
    }
}

// ---------------------------------------------------------------------------
// Main GEMM + fused GELU/GEMV epilogue — all-register, barrier-free mainloop
// ---------------------------------------------------------------------------
__device__ __forceinline__ void loadA(uint4* a, const char* Ap) {
#pragma unroll
    for (int mi = 0; mi < 4; mi++)
        a[mi] = *reinterpret_cast<const uint4*>(Ap + mi * A_M16_STRIDE);
}
__device__ __forceinline__ void loadB(uint4* b, const char* Bp) {
    b[0] = *reinterpret_cast<const uint4*>(Bp);
    b[1] = *reinterpret_cast<const uint4*>(Bp + B_N16_STRIDE);
}
__device__ __forceinline__ void mmastep(float acc[4][4][4], uint4* a, uint4* b) {
    uint2 bv[4];
    bv[0] = make_uint2(b[0].x, b[0].y);
    bv[1] = make_uint2(b[0].z, b[0].w);
    bv[2] = make_uint2(b[1].x, b[1].y);
    bv[3] = make_uint2(b[1].z, b[1].w);
#pragma unroll
    for (int mi = 0; mi < 4; mi++)
#pragma unroll
        for (int nj = 0; nj < 4; nj++)
            mma16816(acc[mi][nj], reinterpret_cast<uint32_t*>(&a[mi]), bv[nj]);
}

__global__ void __launch_bounds__(THREADS, 4)
gemm_kernel(const float* __restrict__ b1, const float* __restrict__ W2,
            float* __restrict__ out) {
    __shared__ float par[128];          // b1[0:64] | w2[64:128]
    const int tid = threadIdx.x;
    const int wid = tid >> 5;
    const int lid = tid & 31;
    const int wm  = wid >> 1;           // M slab (64 rows), 0..1
    const int wn  = wid & 1;            // N slab (32 cols), 0..1

    // Supertile swizzle: 8(M) x 16(N) CTAs per 128-CTA group
    int cta    = blockIdx.x;
    int super  = cta >> 7;
    int within = cta & 127;
    int m_tile = (super & 7) * 8 + (within & 7);     // 0..63
    int n_tile = (super >> 3) * 16 + (within >> 3);  // 0..255
    int m0     = m_tile * BM;
    int q      = n_tile >> 4;
    int nn     = (n_tile & 15) * BN;

    // Fragment base pointers (advance by one k16 stride per step)
    const char* Ap = (const char*)g_Xf
                   + (size_t)(m_tile * 8 + wm * 4) * A_M16_STRIDE + lid * 16;
    const char* Bp = (const char*)g_Wf
                   + ((size_t)(n_tile * 4 + wn * 2) * 32 + lid) * 16;

    // Epilogue params (single barrier of the whole kernel)
    {
        int col = tid & 63;
        const float* src = (tid < 64) ? b1 : W2;
        par[tid] = src[q * HALF_DIM + nn + col];
    }
    __syncthreads();

    float acc[4][4][4];
#pragma unroll
    for (int mi = 0; mi < 4; mi++)
#pragma unroll
        for (int nj = 0; nj < 4; nj++)
#pragma unroll
            for (int e = 0; e < 4; e++) acc[mi][nj][e] = 0.0f;

    // Register double-buffer, prefetch distance 1, peeled tail (last load is
    // step 127 exactly — no OOB prefetch).
    uint4 a0[4], a1[4];
    uint4 b0[2], b1f[2];
    loadA(a0, Ap); loadB(b0, Bp);
    Ap += A_K16_STRIDE; Bp += B_K16_STRIDE;

    for (int s = 0; s < KSTEPS - 2; s += 2) {
        loadA(a1, Ap); loadB(b1f, Bp);
        Ap += A_K16_STRIDE; Bp += B_K16_STRIDE;
        mmastep(acc, a0, b0);
        loadA(a0, Ap); loadB(b0, Bp);
        Ap += A_K16_STRIDE; Bp += B_K16_STRIDE;
        mmastep(acc, a1, b1f);
    }
    loadA(a1, Ap); loadB(b1f, Bp);      // step 127
    mmastep(acc, a0, b0);               // step 126
    mmastep(acc, a1, b1f);              // step 127

    // Epilogue: h = acc + b1; gelu(h) = h * Phi(h); dot with W2; quad-reduce.
    const float* b1s = par;
    const float* w2s = par + 64;
#pragma unroll
    for (int mi = 0; mi < 4; mi++) {
#pragma unroll
        for (int rh = 0; rh < 2; rh++) {
            float v = 0.0f;
#pragma unroll
            for (int nj = 0; nj < 4; nj++) {
                int ncol = wn * 32 + nj * 8 + 2 * (lid & 3);
#pragma unroll
                for (int e = 0; e < 2; e++) {
                    float h = acc[mi][nj][rh * 2 + e] + b1s[ncol + e];
                    v += h * normcdff(h) * w2s[ncol + e];
                }
            }
            v += __shfl_xor_sync(0xFFFFFFFFu, v, 1);
            v += __shfl_xor_sync(0xFFFFFFFFu, v, 2);
            if ((lid & 3) == 0) {
                int mrow = m0 + wm * 64 + mi * 16 + rh * 8 + (lid >> 2);
                atomicAdd(out + (size_t)mrow * NQ + q, v);
            }
        }
    }
}

// ---------------------------------------------------------------------------
// Launch
// ---------------------------------------------------------------------------
extern "C" void kernel_launch(void* const* d_in, const int* in_sizes, int n_in,
                              void* d_out, int out_size) {
    const float* x  = (const float*)d_in[0];
    const float* W1 = (const float*)d_in[1];
    const float* b1 = (const float*)d_in[2];
    const float* W2 = (const float*)d_in[3];
    const float* b2 = (const float*)d_in[4];
    float* out = (float*)d_out;
    (void)in_sizes; (void)n_in; (void)out_size;

    prep_all_kernel<<<12800, 256, PREP_SMEM>>>(W1, x, out, b2);
    gemm_kernel<<<NTILES, THREADS>>>(b1, W2, out);
}

// round 15
// speedup vs baseline: 1.5519x; 1.0010x over previous
#include <cuda_runtime.h>
#include <cuda_fp16.h>
#include <cstdint>

// ---------------------------------------------------------------------------
// Problem constants
// ---------------------------------------------------------------------------
#define BATCH    8192
#define HIDDEN   2048
#define NQ       16
#define HALF_DIM 1024

// GEMM tiling: CTA 128(M)x64(N), 4 warps (2Mx2N of 64x32), 4 CTAs/SM.
// BOTH operands fragment-major in gmem -> LDG.CONSTANT straight to registers.
// Register double-buffer, barrier-free mainloop (R14 measured-best + __ldg).
#define BM      128
#define BN      64
#define THREADS 128
#define M_TILES (BATCH / BM)            // 64
#define N_TILES (NQ * HALF_DIM / BN)    // 256
#define NTILES  (M_TILES * N_TILES)     // 16384
#define KSTEPS  (HIDDEN / 16)           // 128 k16 steps

// Fragment record strides (bytes)
//   A record (m16,k16): 32 lanes x 16B = 512B; addr = (m16*128 + k16)*512 + lane*16
//   B record (k16,n16): 32 lanes x 16B = 512B; addr = (k16*1024 + n16)*512 + lane*16
//     lane 16B = {n8even.r0, n8even.r1, n8odd.r0, n8odd.r1}
#define A_K16_STRIDE 512u
#define A_M16_STRIDE 65536u             // 128 * 512
#define B_N16_STRIDE 512u
#define B_K16_STRIDE 524288u            // 1024 * 512

// fp16 fragment scratch
__device__ __align__(1024) __half g_Xf[(size_t)BATCH * HIDDEN + 512];
__device__ __align__(1024) __half g_Wf[(size_t)NQ * HALF_DIM * HIDDEN + 8192];

// ---------------------------------------------------------------------------
// Helpers
// ---------------------------------------------------------------------------
__device__ __forceinline__ void mma16816(float* c, const uint32_t* a, uint2 b) {
    asm volatile(
        "mma.sync.aligned.m16n8k16.row.col.f32.f16.f16.f32 "
        "{%0,%1,%2,%3}, {%4,%5,%6,%7}, {%8,%9}, {%0,%1,%2,%3};"
        : "+f"(c[0]), "+f"(c[1]), "+f"(c[2]), "+f"(c[3])
        : "r"(a[0]), "r"(a[1]), "r"(a[2]), "r"(a[3]), "r"(b.x), "r"(b.y));
}

// ---------------------------------------------------------------------------
// Fused prepass: one launch, block-range dispatch (R14, at DRAM floor).
//   blocks [0, 8192)      : W1 -> B fragment records (smem-tiled, coalesced)
//   blocks [8192, 12288)  : x  -> A fragment records (smem-tiled, coalesced)
//   blocks [12288, 12800) : out = b2 broadcast
// ---------------------------------------------------------------------------
#define PS 260                            // smem row stride (floats)
#define PREP_SMEM (16 * PS * 4)           // 16640 bytes

__global__ void prep_all_kernel(const float* __restrict__ W1,
                                const float* __restrict__ x,
                                float* __restrict__ out,
                                const float* __restrict__ b2) {
    extern __shared__ float s[];
    int bid = blockIdx.x;
    int t   = threadIdx.x;                // 256 threads

    if (bid < 8192) {
        // ---- W prep: block = (nb, k16, q) ----
        int nb  = bid & 3;
        int k16 = (bid >> 2) & 127;
        int q   = bid >> 9;
        const float* src = W1 + ((size_t)q * HIDDEN + k16 * 16) * HALF_DIM + nb * 256;
#pragma unroll
        for (int i = 0; i < 16; i++)
            s[i * PS + t] = src[(size_t)i * HALF_DIM + t];
        __syncthreads();
        int lane = t & 31;
        int w    = t >> 5;
#pragma unroll
        for (int p = 0; p < 2; p++) {
            int n16l = w * 2 + p;                   // 0..15
            int nl   = n16l * 16 + (lane >> 2);     // n8even col within 256
            int kb   = (lane & 3) << 1;
            union { __half2 h; uint32_t u; } e0, e1, o0, o1;
            e0.h = __floats2half2_rn(s[(kb + 0) * PS + nl],     s[(kb + 1) * PS + nl]);
            e1.h = __floats2half2_rn(s[(kb + 8) * PS + nl],     s[(kb + 9) * PS + nl]);
            o0.h = __floats2half2_rn(s[(kb + 0) * PS + nl + 8], s[(kb + 1) * PS + nl + 8]);
            o1.h = __floats2half2_rn(s[(kb + 8) * PS + nl + 8], s[(kb + 9) * PS + nl + 8]);
            int n16g = q * 64 + nb * 16 + n16l;     // 0..1023
            reinterpret_cast<uint4*>(g_Wf)[((size_t)k16 * 1024 + n16g) * 32 + lane] =
                make_uint4(e0.u, e1.u, o0.u, o1.u);
        }
    } else if (bid < 12288) {
        // ---- X prep: block = (m16, kb of 256 cols) ----
        int idx = bid - 8192;
        int m16 = idx >> 3;
        int kb  = idx & 7;
        const float* src = x + (size_t)(m16 * 16) * HIDDEN + kb * 256;
#pragma unroll
        for (int i = 0; i < 16; i++)
            s[i * PS + t] = src[(size_t)i * HIDDEN + t];
        __syncthreads();
        int lane = t & 31;
        int w    = t >> 5;
#pragma unroll
        for (int p = 0; p < 2; p++) {
            int k16l = w * 2 + p;                   // 0..15
            int r    = lane >> 2;
            int base = k16l * 16 + ((lane & 3) << 1);
            union { __half2 h; uint32_t u; } a0, a1, a2, a3;
            a0.h = __floats2half2_rn(s[r * PS + base],           s[r * PS + base + 1]);
            a1.h = __floats2half2_rn(s[(r + 8) * PS + base],     s[(r + 8) * PS + base + 1]);
            a2.h = __floats2half2_rn(s[r * PS + base + 8],       s[r * PS + base + 9]);
            a3.h = __floats2half2_rn(s[(r + 8) * PS + base + 8], s[(r + 8) * PS + base + 9]);
            int rec = m16 * 128 + kb * 16 + k16l;
            reinterpret_cast<uint4*>(g_Xf)[(size_t)rec * 32 + lane] =
                make_uint4(a0.u, a1.u, a2.u, a3.u);
        }
    } else {
        // ---- out init ----
        int i = (bid - 12288) * 256 + t;
        out[i] = b2[i & (NQ - 1)];
    }
}

// ---------------------------------------------------------------------------
// Main GEMM + fused GELU/GEMV epilogue — all-register, barrier-free mainloop
// ---------------------------------------------------------------------------
__device__ __forceinline__ void loadAB(uint4* a, uint4* b,
                                       const char* Ap, const char* Bp) {
    // B first: B lines are shared by twin warps (wm=0/1) — early issue raises
    // the L1-hit chance for the second reader.
    b[0] = __ldg(reinterpret_cast<const uint4*>(Bp));
    b[1] = __ldg(reinterpret_cast<const uint4*>(Bp + B_N16_STRIDE));
#pragma unroll
    for (int mi = 0; mi < 4; mi++)
        a[mi] = __ldg(reinterpret_cast<const uint4*>(Ap + mi * A_M16_STRIDE));
}
__device__ __forceinline__ void mmastep(float acc[4][4][4], uint4* a, uint4* b) {
    const uint2* bv = reinterpret_cast<const uint2*>(b);   // register alias, no copies
#pragma unroll
    for (int mi = 0; mi < 4; mi++)
#pragma unroll
        for (int nj = 0; nj < 4; nj++)
            mma16816(acc[mi][nj], reinterpret_cast<uint32_t*>(&a[mi]), bv[nj]);
}

__global__ void __launch_bounds__(THREADS, 4)
gemm_kernel(const float* __restrict__ b1, const float* __restrict__ W2,
            float* __restrict__ out) {
    __shared__ float par[128];          // b1[0:64] | w2[64:128]
    const int tid = threadIdx.x;
    const int wid = tid >> 5;
    const int lid = tid & 31;
    const int wm  = wid >> 1;           // M slab (64 rows), 0..1
    const int wn  = wid & 1;            // N slab (32 cols), 0..1

    // Supertile swizzle: 8(M) x 16(N) CTAs per 128-CTA group
    int cta    = blockIdx.x;
    int super  = cta >> 7;
    int within = cta & 127;
    int m_tile = (super & 7) * 8 + (within & 7);     // 0..63
    int n_tile = (super >> 3) * 16 + (within >> 3);  // 0..255
    int m0     = m_tile * BM;
    int q      = n_tile >> 4;
    int nn     = (n_tile & 15) * BN;

    // Fragment base pointers (advance by one k16 stride per step)
    const char* Ap = (const char*)g_Xf
                   + (size_t)(m_tile * 8 + wm * 4) * A_M16_STRIDE + lid * 16;
    const char* Bp = (const char*)g_Wf
                   + ((size_t)(n_tile * 4 + wn * 2) * 32 + lid) * 16;

    // Epilogue params (single barrier of the whole kernel)
    {
        int col = tid & 63;
        const float* src = (tid < 64) ? b1 : W2;
        par[tid] = src[q * HALF_DIM + nn + col];
    }
    __syncthreads();

    float acc[4][4][4];
#pragma unroll
    for (int mi = 0; mi < 4; mi++)
#pragma unroll
        for (int nj = 0; nj < 4; nj++)
#pragma unroll
            for (int e = 0; e < 4; e++) acc[mi][nj][e] = 0.0f;

    // Register double-buffer, prefetch distance 1, peeled tail (last load is
    // step 127 exactly — no OOB prefetch).
    uint4 a0[4], a1[4];
    uint4 b0[2], b1f[2];
    loadAB(a0, b0, Ap, Bp);
    Ap += A_K16_STRIDE; Bp += B_K16_STRIDE;

    for (int s = 0; s < KSTEPS - 2; s += 2) {
        loadAB(a1, b1f, Ap, Bp);
        Ap += A_K16_STRIDE; Bp += B_K16_STRIDE;
        mmastep(acc, a0, b0);
        loadAB(a0, b0, Ap, Bp);
        Ap += A_K16_STRIDE; Bp += B_K16_STRIDE;
        mmastep(acc, a1, b1f);
    }
    loadAB(a1, b1f, Ap, Bp);            // step 127
    mmastep(acc, a0, b0);               // step 126
    mmastep(acc, a1, b1f);              // step 127

    // Epilogue: h = acc + b1; gelu(h) = h * Phi(h); dot with W2; quad-reduce.
    const float* b1s = par;
    const float* w2s = par + 64;
#pragma unroll
    for (int mi = 0; mi < 4; mi++) {
#pragma unroll
        for (int rh = 0; rh < 2; rh++) {
            float v = 0.0f;
#pragma unroll
            for (int nj = 0; nj < 4; nj++) {
                int ncol = wn * 32 + nj * 8 + 2 * (lid & 3);
#pragma unroll
                for (int e = 0; e < 2; e++) {
                    float h = acc[mi][nj][rh * 2 + e] + b1s[ncol + e];
                    v += h * normcdff(h) * w2s[ncol + e];
                }
            }
            v += __shfl_xor_sync(0xFFFFFFFFu, v, 1);
            v += __shfl_xor_sync(0xFFFFFFFFu, v, 2);
            if ((lid & 3) == 0) {
                int mrow = m0 + wm * 64 + mi * 16 + rh * 8 + (lid >> 2);
                atomicAdd(out + (size_t)mrow * NQ + q, v);
            }
        }
    }
}

// ---------------------------------------------------------------------------
// Launch
// ---------------------------------------------------------------------------
extern "C" void kernel_launch(void* const* d_in, const int* in_sizes, int n_in,
                              void* d_out, int out_size) {
    const float* x  = (const float*)d_in[0];
    const float* W1 = (const float*)d_in[1];
    const float* b1 = (const float*)d_in[2];
    const float* W2 = (const float*)d_in[3];
    const float* b2 = (const float*)d_in[4];
    float* out = (float*)d_out;
    (void)in_sizes; (void)n_in; (void)out_size;

    prep_all_kernel<<<12800, 256, PREP_SMEM>>>(W1, x, out, b2);
    gemm_kernel<<<NTILES, THREADS>>>(b1, W2, out);
}